// round 2
// baseline (speedup 1.0000x reference)
#include <cuda_runtime.h>
#include <math.h>

#define NB 4
#define NC 256
#define NHEADS 8
#define NLEVELS 4
#define NPOINTS 4
#define NHQ 64
#define NWQ 64
#define NPIX 4096
#define NHD 32
#define TOTPIX (4096+1024+256+64)

// scratch (allocation-free rule: __device__ globals)
__device__ float g_q[NB*NC*NPIX];          // q projection, CHW
__device__ float g_off[NB*NC*NPIX];        // tanh'd offsets, CHW
__device__ float g_logit[NB*NHEADS*16*NPIX]; // logits -> softmax in place
__device__ float g_v[NB*TOTPIX*NC];        // per level: [b][p][c] pixel-major
__device__ float g_agg[NB*NC*NPIX];        // aggregated sampled output, CHW

// ---------------------------------------------------------------------------
// Generic 64x64x16 SGEMM: Y = W(256 x K=256) * X(256 x N), batched over z.
// mode 0: Y = g_q (store CHW)
// mode 1: Y = g_v + vbase, store pixel-major [b][p][c]
// mode 2: out-projection: +residual, BN, SiLU -> Yp (d_out)
// ---------------------------------------------------------------------------
__global__ void k_gemm(const float* __restrict__ W, const float* __restrict__ X,
                       float* __restrict__ Yp, int N, int mode,
                       const float* __restrict__ query,
                       const float* __restrict__ gamma, const float* __restrict__ beta,
                       const float* __restrict__ mean, const float* __restrict__ var,
                       size_t vbase)
{
    const int K = 256;
    int b  = blockIdx.z;
    int m0 = blockIdx.y * 64;
    int n0 = blockIdx.x * 64;
    const float* Xb = (mode == 2) ? (g_agg + (size_t)b * K * N)
                                  : (X + (size_t)b * K * N);

    __shared__ float As[16][64];
    __shared__ float Bs[16][64];

    int tid = threadIdx.x;
    int rm = tid & 15, rn = tid >> 4;
    int am = tid >> 2, ak = (tid & 3) * 4;
    int bk = tid >> 4, bn = (tid & 15) * 4;

    float acc[4][4] = {};

    for (int k0 = 0; k0 < K; k0 += 16) {
        float4 a4 = *(const float4*)&W[(size_t)(m0 + am) * K + k0 + ak];
        As[ak+0][am] = a4.x; As[ak+1][am] = a4.y;
        As[ak+2][am] = a4.z; As[ak+3][am] = a4.w;
        float4 b4 = *(const float4*)&Xb[(size_t)(k0 + bk) * N + n0 + bn];
        *(float4*)&Bs[bk][bn] = b4;
        __syncthreads();
        #pragma unroll
        for (int k = 0; k < 16; k++) {
            float4 av = *(float4*)&As[k][rm * 4];
            float4 bv = *(float4*)&Bs[k][rn * 4];
            float aa[4] = {av.x, av.y, av.z, av.w};
            float bb[4] = {bv.x, bv.y, bv.z, bv.w};
            #pragma unroll
            for (int i = 0; i < 4; i++)
                #pragma unroll
                for (int j = 0; j < 4; j++)
                    acc[i][j] += aa[i] * bb[j];
        }
        __syncthreads();
    }

    #pragma unroll
    for (int i = 0; i < 4; i++) {
        int m = m0 + rm * 4 + i;
        #pragma unroll
        for (int j = 0; j < 4; j++) {
            int n = n0 + rn * 4 + j;
            float v = acc[i][j];
            if (mode == 0) {
                g_q[((size_t)b * NC + m) * N + n] = v;
            } else if (mode == 1) {
                g_v[vbase + ((size_t)b * N + n) * NC + m] = v;
            } else {
                float x  = v + query[((size_t)b * NC + m) * N + n];
                float inv = rsqrtf(var[m] + 1e-5f);
                float xn = (x - mean[m]) * gamma[m] * inv + beta[m];
                Yp[((size_t)b * NC + m) * N + n] = xn / (1.f + __expf(-xn));
            }
        }
    }
}

// ---------------------------------------------------------------------------
// Fused 3x3 conv over g_q: 384 output channels (256 offsets + 128 logits),
// implicit GEMM, K = 256*9. Pixel tile = one image row (64 px). Epilogue
// applies bias and tanh*0.25 on the offset half.
// ---------------------------------------------------------------------------
__global__ void k_conv(const float* __restrict__ off_w, const float* __restrict__ attn_w,
                       const float* __restrict__ off_b, const float* __restrict__ attn_b)
{
    const int K = 2304;
    int b  = blockIdx.z;
    int m0 = blockIdx.y * 64;     // out channel tile (0..383)
    int y  = blockIdx.x;          // image row; n0 = y*64
    const float* Q = g_q + (size_t)b * NC * NPIX;

    __shared__ float As[16][64];
    __shared__ float Bs[16][64];

    int tid = threadIdx.x;
    int rm = tid & 15, rn = tid >> 4;
    int am = tid >> 2, ak = (tid & 3) * 4;
    int bk = tid >> 4, bn = (tid & 15) * 4;

    int mg = m0 + am;
    const float* Wrow = (mg < 256) ? (off_w + (size_t)mg * K)
                                   : (attn_w + (size_t)(mg - 256) * K);

    float acc[4][4] = {};

    for (int k0 = 0; k0 < K; k0 += 16) {
        float4 a4 = *(const float4*)&Wrow[k0 + ak];
        As[ak+0][am] = a4.x; As[ak+1][am] = a4.y;
        As[ak+2][am] = a4.z; As[ak+3][am] = a4.w;

        int kg  = k0 + bk;
        int cch = kg / 9, tap = kg % 9;
        int dy = tap / 3 - 1, dx = tap % 3 - 1;
        int sy = y + dy;
        bool rowok = (sy >= 0) && (sy < 64);
        const float* qrow = Q + (size_t)cch * NPIX + sy * 64;
        #pragma unroll
        for (int j = 0; j < 4; j++) {
            int sx = bn + j + dx;
            Bs[bk][bn + j] = (rowok && sx >= 0 && sx < 64) ? qrow[sx] : 0.f;
        }
        __syncthreads();
        #pragma unroll
        for (int k = 0; k < 16; k++) {
            float4 av = *(float4*)&As[k][rm * 4];
            float4 bv = *(float4*)&Bs[k][rn * 4];
            float aa[4] = {av.x, av.y, av.z, av.w};
            float bb[4] = {bv.x, bv.y, bv.z, bv.w};
            #pragma unroll
            for (int i = 0; i < 4; i++)
                #pragma unroll
                for (int j = 0; j < 4; j++)
                    acc[i][j] += aa[i] * bb[j];
        }
        __syncthreads();
    }

    #pragma unroll
    for (int i = 0; i < 4; i++) {
        int m = m0 + rm * 4 + i;
        #pragma unroll
        for (int j = 0; j < 4; j++) {
            int n = y * 64 + rn * 4 + j;
            float v = acc[i][j];
            if (m < 256) {
                g_off[((size_t)b * NC + m) * NPIX + n] = tanhf(v + off_b[m]) * 0.25f;
            } else {
                g_logit[((size_t)b * 128 + (m - 256)) * NPIX + n] = v + attn_b[m - 256];
            }
        }
    }
}

// softmax over the 16 (level,point) logits per (b, head, pixel); in place.
__global__ void k_softmax()
{
    int t = blockIdx.x * blockDim.x + threadIdx.x;   // 0..131071
    int p = t & (NPIX - 1);
    int r = t >> 12;                                  // b*8+h
    float* base = g_logit + (size_t)r * 16 * NPIX + p;
    float vals[16];
    float mx = -1e30f;
    #pragma unroll
    for (int i = 0; i < 16; i++) { vals[i] = base[(size_t)i * NPIX]; mx = fmaxf(mx, vals[i]); }
    float s = 0.f;
    #pragma unroll
    for (int i = 0; i < 16; i++) { vals[i] = __expf(vals[i] - mx); s += vals[i]; }
    float inv = 1.f / s;
    #pragma unroll
    for (int i = 0; i < 16; i++) base[(size_t)i * NPIX] = vals[i] * inv;
}

// ---------------------------------------------------------------------------
// Deformable sampling. One warp per query pixel; lane = head-dim channel.
// v is pixel-major [b][p][256] so lane gathers are one 128B line.
// smem transpose for coalesced CHW output store.
// ---------------------------------------------------------------------------
__global__ void k_sample()
{
    int bh = blockIdx.y;
    int b = bh >> 3, h = bh & 7;
    int p0 = blockIdx.x * 32;
    int warp = threadIdx.x >> 5, lane = threadIdx.x & 31;
    int p = p0 + warp;
    int py = p >> 6, px = p & 63;
    float refx = -1.f + 2.f * px / 63.f;
    float refy = -1.f + 2.f * py / 63.f;

    const float* offb = g_off + (size_t)b * NC * NPIX + p;
    const float* attb = g_logit + (size_t)(b * 8 + h) * 16 * NPIX + p;

    float acc = 0.f;
    size_t base = 0;
    int wl = 64;
    #pragma unroll
    for (int lvl = 0; lvl < 4; lvl++) {
        int npix = wl * wl;
        const float* vb = g_v + base + (size_t)b * npix * NC + h * 32 + lane;
        float sw = 0.5f * (wl - 1);
        #pragma unroll
        for (int pt = 0; pt < 4; pt++) {
            int cho = ((h * 4 + lvl) * 4 + pt) * 2;
            float ox = offb[(size_t)cho * NPIX];
            float oy = offb[(size_t)(cho + 1) * NPIX];
            float a  = attb[(size_t)(lvl * 4 + pt) * NPIX];
            float fx = (refx + ox + 1.f) * sw;
            float fy = (refy + oy + 1.f) * sw;
            float x0f = floorf(fx), y0f = floorf(fy);
            float wx1 = fx - x0f, wx0 = 1.f - wx1;
            float wy1 = fy - y0f, wy0 = 1.f - wy1;
            int x0 = (int)x0f, y0 = (int)y0f;
            int x1 = x0 + 1, y1 = y0 + 1;
            float sv = 0.f;
            if (x0 >= 0 && x0 < wl && y0 >= 0 && y0 < wl) sv += wx0 * wy0 * vb[(size_t)(y0 * wl + x0) * NC];
            if (x1 >= 0 && x1 < wl && y0 >= 0 && y0 < wl) sv += wx1 * wy0 * vb[(size_t)(y0 * wl + x1) * NC];
            if (x0 >= 0 && x0 < wl && y1 >= 0 && y1 < wl) sv += wx0 * wy1 * vb[(size_t)(y1 * wl + x0) * NC];
            if (x1 >= 0 && x1 < wl && y1 >= 0 && y1 < wl) sv += wx1 * wy1 * vb[(size_t)(y1 * wl + x1) * NC];
            acc += a * sv;
        }
        base += (size_t)NB * npix * NC;
        wl >>= 1;
    }

    __shared__ float s[32][33];
    s[warp][lane] = acc;
    __syncthreads();
    // coalesced CHW write: thread (warp=d, lane=pixel)
    g_agg[((size_t)b * NC + h * 32 + warp) * NPIX + p0 + lane] = s[lane][warp];
}

extern "C" void kernel_launch(void* const* d_in, const int* in_sizes, int n_in,
                              void* d_out, int out_size)
{
    const float* query  = (const float*)d_in[0];
    const float* feat[4] = {(const float*)d_in[1], (const float*)d_in[2],
                            (const float*)d_in[3], (const float*)d_in[4]};
    const float* q_w    = (const float*)d_in[5];
    const float* v_w    = (const float*)d_in[6];
    const float* out_w  = (const float*)d_in[7];
    const float* off_w  = (const float*)d_in[8];
    const float* off_b  = (const float*)d_in[9];
    const float* attn_w = (const float*)d_in[10];
    const float* attn_b = (const float*)d_in[11];
    const float* gamma  = (const float*)d_in[12];
    const float* beta   = (const float*)d_in[13];
    const float* mean   = (const float*)d_in[14];
    const float* var    = (const float*)d_in[15];

    dim3 blk(256);

    // 1. q projection
    k_gemm<<<dim3(64, 4, NB), blk>>>(q_w, query, nullptr, NPIX, 0,
                                     nullptr, nullptr, nullptr, nullptr, nullptr, 0);
    // 2. fused 3x3 conv (offsets + logits)
    k_conv<<<dim3(64, 6, NB), blk>>>(off_w, attn_w, off_b, attn_b);
    // 3. softmax over level*point
    k_softmax<<<512, 256>>>();
    // 4. v projections per level (pixel-major layout)
    size_t vbase = 0;
    for (int lvl = 0; lvl < 4; lvl++) {
        int wl = 64 >> lvl;
        int np = wl * wl;
        k_gemm<<<dim3(np / 64, 4, NB), blk>>>(v_w + (size_t)lvl * 256 * 256, feat[lvl],
                                              nullptr, np, 1,
                                              nullptr, nullptr, nullptr, nullptr, nullptr,
                                              vbase);
        vbase += (size_t)NB * np * NC;
    }
    // 5. deformable sampling + aggregation
    k_sample<<<dim3(128, 32), 1024>>>();
    // 6. output projection + residual + BN + SiLU
    k_gemm<<<dim3(64, 4, NB), blk>>>(out_w, nullptr, (float*)d_out, NPIX, 2,
                                     query, gamma, beta, mean, var, 0);
}